// round 1
// baseline (speedup 1.0000x reference)
#include <cuda_runtime.h>
#include <cuda_fp8.h>
#include <cuda_fp16.h>
#include <math.h>

// Problem dims (fixed by setup_inputs)
#define Bb 2
#define Tt 1024
#define Cdim 2048
#define Hh 16
#define HDim 128
#define MLPD 8192
#define Mrows (Bb * Tt)   // 2048 tokens

// ---------------------------------------------------------------------------
// Scratch (static __device__ arrays — allocation-guard safe)
// ---------------------------------------------------------------------------
__device__ float g_xdq[Mrows * Cdim];            // 16 MB  (quantize-dequantize buffer)
__device__ float g_q[Mrows * Cdim];              // 16 MB
__device__ float g_k[Mrows * Cdim];              // 16 MB
__device__ float g_v[Mrows * Cdim];              // 16 MB
__device__ float g_scores[(size_t)Bb * Hh * Tt * Tt];  // 128 MB
__device__ float g_ctx[Mrows * Cdim];            // 16 MB
__device__ float g_tmp[Mrows * Cdim];            // 16 MB  (attn_out / ffn out)
__device__ float g_x1[Mrows * Cdim];             // 16 MB  (post-ln1)
__device__ float g_h[Mrows * MLPD];              // 64 MB  (fc1 out, post-gelu)
__device__ float g_hdq[Mrows * MLPD];            // 64 MB
__device__ float g_ffn[Mrows * Cdim];            // 16 MB

// ---------------------------------------------------------------------------
// fp8 quantize-dequantize: per 128-wide block along last dim.
// Matches reference: s = max(amax/fmax, 1e-12); q = fp8(x / s); out = f32(q)*s
// ---------------------------------------------------------------------------
__device__ __forceinline__ float qdq_one(float x, float s, int e4m3) {
    float r = x / s;  // true IEEE divide to match jnp (xb / s)
    __nv_fp8_storage_t q = __nv_cvt_float_to_fp8(
        r, __NV_SATFINITE, e4m3 ? __NV_E4M3 : __NV_E5M2);
    __half_raw hr = __nv_cvt_fp8_to_halfraw(q, e4m3 ? __NV_E4M3 : __NV_E5M2);
    __half h = *reinterpret_cast<__half*>(&hr);
    return __half2float(h) * s;
}

// one warp per 128-element block; 8 warps per CTA
__global__ void qdq_kernel(const float* __restrict__ in, float* __restrict__ out,
                           float fmax, int e4m3)
{
    int blk  = blockIdx.x * 8 + (threadIdx.x >> 5);
    int lane = threadIdx.x & 31;
    size_t base = (size_t)blk * 128 + (size_t)lane * 4;
    float4 v = *reinterpret_cast<const float4*>(in + base);
    float am = fmaxf(fmaxf(fabsf(v.x), fabsf(v.y)), fmaxf(fabsf(v.z), fabsf(v.w)));
    #pragma unroll
    for (int o = 16; o > 0; o >>= 1)
        am = fmaxf(am, __shfl_xor_sync(0xffffffffu, am, o));
    float s = fmaxf(am / fmax, 1e-12f);
    float4 r;
    r.x = qdq_one(v.x, s, e4m3);
    r.y = qdq_one(v.y, s, e4m3);
    r.z = qdq_one(v.z, s, e4m3);
    r.w = qdq_one(v.w, s, e4m3);
    *reinterpret_cast<float4*>(out + base) = r;
}

// ---------------------------------------------------------------------------
// Tiled SGEMM, NT: C[m,n] = sum_k A[m,k] * W[n,k]  (both row-major)
// 128x128 block tile, BK=8, 256 threads, 8x8 per thread.
// Batched via blockIdx.z with decomposed offsets: z1 = z/zdiv, z2 = z%zdiv.
// Epilogue: optional per-128-out-block weight scale, bias, exact-erf GELU.
// All dims assumed multiples of the tile (true for this problem).
// ---------------------------------------------------------------------------
__global__ void __launch_bounds__(256)
gemm_nt(const float* __restrict__ A, const float* __restrict__ W, float* __restrict__ C,
        int K, int lda, int ldb, int ldc,
        int zdiv, long long sA1, long long sA2, long long sB1, long long sB2,
        long long sC1, long long sC2,
        const float* __restrict__ wscale, const float* __restrict__ bias, int act)
{
    __shared__ float As[8][132];
    __shared__ float Bs[8][132];

    int z = blockIdx.z;
    int z1 = z / zdiv, z2 = z % zdiv;
    A += z1 * sA1 + z2 * sA2;
    W += z1 * sB1 + z2 * sB2;
    C += z1 * sC1 + z2 * sC2;

    int tid = threadIdx.x;
    int tx = tid & 15, ty = tid >> 4;
    int m0 = blockIdx.y * 128, n0 = blockIdx.x * 128;
    int lrow = tid >> 1;          // 0..127
    int lcol = (tid & 1) * 4;     // 0 or 4

    float acc[8][8];
    #pragma unroll
    for (int i = 0; i < 8; i++)
        #pragma unroll
        for (int j = 0; j < 8; j++) acc[i][j] = 0.0f;

    for (int k0 = 0; k0 < K; k0 += 8) {
        float4 av = *reinterpret_cast<const float4*>(A + (size_t)(m0 + lrow) * lda + k0 + lcol);
        float4 bv = *reinterpret_cast<const float4*>(W + (size_t)(n0 + lrow) * ldb + k0 + lcol);
        As[lcol + 0][lrow] = av.x; As[lcol + 1][lrow] = av.y;
        As[lcol + 2][lrow] = av.z; As[lcol + 3][lrow] = av.w;
        Bs[lcol + 0][lrow] = bv.x; Bs[lcol + 1][lrow] = bv.y;
        Bs[lcol + 2][lrow] = bv.z; Bs[lcol + 3][lrow] = bv.w;
        __syncthreads();
        #pragma unroll
        for (int kk = 0; kk < 8; kk++) {
            float4 a0 = *reinterpret_cast<const float4*>(&As[kk][ty * 8]);
            float4 a1 = *reinterpret_cast<const float4*>(&As[kk][ty * 8 + 4]);
            float4 b0 = *reinterpret_cast<const float4*>(&Bs[kk][tx * 8]);
            float4 b1 = *reinterpret_cast<const float4*>(&Bs[kk][tx * 8 + 4]);
            float a[8] = {a0.x, a0.y, a0.z, a0.w, a1.x, a1.y, a1.z, a1.w};
            float b[8] = {b0.x, b0.y, b0.z, b0.w, b1.x, b1.y, b1.z, b1.w};
            #pragma unroll
            for (int i = 0; i < 8; i++)
                #pragma unroll
                for (int j = 0; j < 8; j++) acc[i][j] = fmaf(a[i], b[j], acc[i][j]);
        }
        __syncthreads();
    }

    #pragma unroll
    for (int i = 0; i < 8; i++) {
        int m = m0 + ty * 8 + i;
        #pragma unroll
        for (int j = 0; j < 8; j++) {
            int n = n0 + tx * 8 + j;
            float vv = acc[i][j];
            if (wscale) vv *= wscale[n >> 7];
            if (bias)   vv += bias[n];
            if (act)    vv = 0.5f * vv * (1.0f + erff(vv * 0.7071067811865476f));
            C[(size_t)m * ldc + n] = vv;
        }
    }
}

// ---------------------------------------------------------------------------
// Tiled SGEMM, NN: C[m,n] = sum_k A[m,k] * B[k,n]   (used for attn @ V)
// ---------------------------------------------------------------------------
__global__ void __launch_bounds__(256)
gemm_nn(const float* __restrict__ A, const float* __restrict__ Bm, float* __restrict__ C,
        int K, int lda, int ldb, int ldc,
        int zdiv, long long sA1, long long sA2, long long sB1, long long sB2,
        long long sC1, long long sC2)
{
    __shared__ float As[8][132];
    __shared__ float Bs[8][132];

    int z = blockIdx.z;
    int z1 = z / zdiv, z2 = z % zdiv;
    A  += z1 * sA1 + z2 * sA2;
    Bm += z1 * sB1 + z2 * sB2;
    C  += z1 * sC1 + z2 * sC2;

    int tid = threadIdx.x;
    int tx = tid & 15, ty = tid >> 4;
    int m0 = blockIdx.y * 128, n0 = blockIdx.x * 128;
    int arow = tid >> 1, acol = (tid & 1) * 4;
    int brow = tid >> 5, bcol = (tid & 31) * 4;

    float acc[8][8];
    #pragma unroll
    for (int i = 0; i < 8; i++)
        #pragma unroll
        for (int j = 0; j < 8; j++) acc[i][j] = 0.0f;

    for (int k0 = 0; k0 < K; k0 += 8) {
        float4 av = *reinterpret_cast<const float4*>(A + (size_t)(m0 + arow) * lda + k0 + acol);
        As[acol + 0][arow] = av.x; As[acol + 1][arow] = av.y;
        As[acol + 2][arow] = av.z; As[acol + 3][arow] = av.w;
        float4 bv = *reinterpret_cast<const float4*>(Bm + (size_t)(k0 + brow) * ldb + n0 + bcol);
        *reinterpret_cast<float4*>(&Bs[brow][bcol]) = bv;
        __syncthreads();
        #pragma unroll
        for (int kk = 0; kk < 8; kk++) {
            float4 a0 = *reinterpret_cast<const float4*>(&As[kk][ty * 8]);
            float4 a1 = *reinterpret_cast<const float4*>(&As[kk][ty * 8 + 4]);
            float4 b0 = *reinterpret_cast<const float4*>(&Bs[kk][tx * 8]);
            float4 b1 = *reinterpret_cast<const float4*>(&Bs[kk][tx * 8 + 4]);
            float a[8] = {a0.x, a0.y, a0.z, a0.w, a1.x, a1.y, a1.z, a1.w};
            float b[8] = {b0.x, b0.y, b0.z, b0.w, b1.x, b1.y, b1.z, b1.w};
            #pragma unroll
            for (int i = 0; i < 8; i++)
                #pragma unroll
                for (int j = 0; j < 8; j++) acc[i][j] = fmaf(a[i], b[j], acc[i][j]);
        }
        __syncthreads();
    }

    #pragma unroll
    for (int i = 0; i < 8; i++) {
        int m = m0 + ty * 8 + i;
        #pragma unroll
        for (int j = 0; j < 8; j++) {
            int n = n0 + tx * 8 + j;
            C[(size_t)m * ldc + n] = acc[i][j];
        }
    }
}

// ---------------------------------------------------------------------------
// Causal-masked softmax over score rows. scale = 1/sqrt(HD) folded in here.
// One CTA (256 threads) per (b,h,q) row of length T=1024.
// ---------------------------------------------------------------------------
__global__ void softmax_kernel(float* __restrict__ S, const int* __restrict__ mask, float scale)
{
    int row = blockIdx.x;               // (b*H + h)*T + q
    int q = row % Tt;
    int b = row / (Hh * Tt);
    float* sr = S + (size_t)row * Tt;
    const int* mr = mask + ((size_t)b * Tt + q) * Tt;
    int tid = threadIdx.x;
    __shared__ float red[256];

    float vals[4];
    float lmax = -INFINITY;
    #pragma unroll
    for (int it = 0; it < 4; it++) {
        int i = tid + it * 256;
        float v = mr[i] ? sr[i] * scale : -INFINITY;
        vals[it] = v;
        lmax = fmaxf(lmax, v);
    }
    red[tid] = lmax; __syncthreads();
    for (int o = 128; o > 0; o >>= 1) {
        if (tid < o) red[tid] = fmaxf(red[tid], red[tid + o]);
        __syncthreads();
    }
    float mx = red[0];
    __syncthreads();

    float lsum = 0.0f;
    #pragma unroll
    for (int it = 0; it < 4; it++) {
        float e = expf(vals[it] - mx);   // exp(-inf - mx) = 0 for masked
        vals[it] = e;
        lsum += e;
    }
    red[tid] = lsum; __syncthreads();
    for (int o = 128; o > 0; o >>= 1) {
        if (tid < o) red[tid] += red[tid + o];
        __syncthreads();
    }
    float inv = 1.0f / red[0];
    #pragma unroll
    for (int it = 0; it < 4; it++) {
        int i = tid + it * 256;
        sr[i] = vals[it] * inv;
    }
}

// ---------------------------------------------------------------------------
// out = LayerNorm(x + y) * (g*repeat(gs)) + (b*repeat(bs)); eps=1e-5, two-pass.
// One CTA per token row (C=2048).
// ---------------------------------------------------------------------------
__global__ void addln_kernel(const float* __restrict__ x, const float* __restrict__ y,
                             float* __restrict__ out,
                             const float* __restrict__ g, const float* __restrict__ gs,
                             const float* __restrict__ b, const float* __restrict__ bs)
{
    int row = blockIdx.x;
    const float* xr = x + (size_t)row * Cdim;
    const float* yr = y + (size_t)row * Cdim;
    float* outr = out + (size_t)row * Cdim;
    __shared__ float buf[Cdim];
    __shared__ float red[256];
    int tid = threadIdx.x;

    float lsum = 0.0f;
    #pragma unroll
    for (int it = 0; it < Cdim / 256; it++) {
        int i = tid + it * 256;
        float v = xr[i] + yr[i];
        buf[i] = v;
        lsum += v;
    }
    red[tid] = lsum; __syncthreads();
    for (int o = 128; o > 0; o >>= 1) {
        if (tid < o) red[tid] += red[tid + o];
        __syncthreads();
    }
    float mean = red[0] * (1.0f / Cdim);
    __syncthreads();

    float lvar = 0.0f;
    #pragma unroll
    for (int it = 0; it < Cdim / 256; it++) {
        int i = tid + it * 256;
        float d = buf[i] - mean;
        lvar += d * d;
    }
    red[tid] = lvar; __syncthreads();
    for (int o = 128; o > 0; o >>= 1) {
        if (tid < o) red[tid] += red[tid + o];
        __syncthreads();
    }
    float rstd = rsqrtf(red[0] * (1.0f / Cdim) + 1e-5f);

    #pragma unroll
    for (int it = 0; it < Cdim / 256; it++) {
        int i = tid + it * 256;
        float d = (buf[i] - mean) * rstd;
        outr[i] = d * (g[i] * gs[i >> 7]) + b[i] * bs[i >> 7];
    }
}

// ---------------------------------------------------------------------------
// Launch pipeline
// ---------------------------------------------------------------------------
extern "C" void kernel_launch(void* const* d_in, const int* in_sizes, int n_in,
                              void* d_out, int out_size)
{
    const float* x     = (const float*)d_in[0];
    const int*   mask  = (const int*)  d_in[1];
    const float* wq    = (const float*)d_in[2];
    const float* qs    = (const float*)d_in[3];
    const float* wk    = (const float*)d_in[4];
    const float* ks    = (const float*)d_in[5];
    const float* wv    = (const float*)d_in[6];
    const float* vs    = (const float*)d_in[7];
    const float* wo    = (const float*)d_in[8];
    const float* os_   = (const float*)d_in[9];
    const float* fc1w  = (const float*)d_in[10];
    const float* fc1s  = (const float*)d_in[11];
    const float* fc1b  = (const float*)d_in[12];
    const float* fc2w  = (const float*)d_in[13];
    const float* fc2s  = (const float*)d_in[14];
    const float* fc2b  = (const float*)d_in[15];
    const float* l1g   = (const float*)d_in[16];
    const float* l1gs  = (const float*)d_in[17];
    const float* l1b   = (const float*)d_in[18];
    const float* l1bs  = (const float*)d_in[19];
    const float* l2g   = (const float*)d_in[20];
    const float* l2gs  = (const float*)d_in[21];
    const float* l2b   = (const float*)d_in[22];
    const float* l2bs  = (const float*)d_in[23];
    float* out = (float*)d_out;

    void* p;
    cudaGetSymbolAddress(&p, g_xdq);    float* xdq = (float*)p;
    cudaGetSymbolAddress(&p, g_q);      float* qb  = (float*)p;
    cudaGetSymbolAddress(&p, g_k);      float* kb  = (float*)p;
    cudaGetSymbolAddress(&p, g_v);      float* vb  = (float*)p;
    cudaGetSymbolAddress(&p, g_scores); float* sc  = (float*)p;
    cudaGetSymbolAddress(&p, g_ctx);    float* ctx = (float*)p;
    cudaGetSymbolAddress(&p, g_tmp);    float* tmp = (float*)p;
    cudaGetSymbolAddress(&p, g_x1);     float* x1  = (float*)p;
    cudaGetSymbolAddress(&p, g_h);      float* hb  = (float*)p;
    cudaGetSymbolAddress(&p, g_hdq);    float* hdq = (float*)p;
    cudaGetSymbolAddress(&p, g_ffn);    float* ffn = (float*)p;

    const float E5MAX = 57344.0f, E4MAX = 448.0f;
    const float INV_SQRT_HD = 0.08838834764831845f;  // 1/sqrt(128)

    // 1. quantize-dequantize x (E5M2)
    qdq_kernel<<<(Mrows * Cdim / 128) / 8, 256>>>(x, xdq, E5MAX, 0);

    // 2. Q/K/V projections: [M,C] = xdq[M,C] @ W[C,C]^T * scale
    dim3 gl(Cdim / 128, Mrows / 128, 1);
    gemm_nt<<<gl, 256>>>(xdq, wq, qb, Cdim, Cdim, Cdim, Cdim,
                         1, 0, 0, 0, 0, 0, 0, qs, nullptr, 0);
    gemm_nt<<<gl, 256>>>(xdq, wk, kb, Cdim, Cdim, Cdim, Cdim,
                         1, 0, 0, 0, 0, 0, 0, ks, nullptr, 0);
    gemm_nt<<<gl, 256>>>(xdq, wv, vb, Cdim, Cdim, Cdim, Cdim,
                         1, 0, 0, 0, 0, 0, 0, vs, nullptr, 0);

    // 3. scores[b,h] = Q_h @ K_h^T   (z = b*H + h)
    dim3 gsc(Tt / 128, Tt / 128, Bb * Hh);
    gemm_nt<<<gsc, 256>>>(qb, kb, sc, HDim, Cdim, Cdim, Tt,
                          Hh,
                          (long long)Tt * Cdim, 128,
                          (long long)Tt * Cdim, 128,
                          (long long)Hh * Tt * Tt, (long long)Tt * Tt,
                          nullptr, nullptr, 0);

    // 4. masked softmax (folds 1/sqrt(HD))
    softmax_kernel<<<Bb * Hh * Tt, 256>>>(sc, mask, INV_SQRT_HD);

    // 5. ctx[b,t,h*HD+d] = attn[b,h] @ V_h
    dim3 gcx(1, Tt / 128, Bb * Hh);
    gemm_nn<<<gcx, 256>>>(sc, vb, ctx, Tt, Tt, Cdim, Cdim,
                          Hh,
                          (long long)Hh * Tt * Tt, (long long)Tt * Tt,
                          (long long)Tt * Cdim, 128,
                          (long long)Tt * Cdim, 128);

    // 6. out projection: qdq(ctx, E5M2) then GEMM
    qdq_kernel<<<(Mrows * Cdim / 128) / 8, 256>>>(ctx, xdq, E5MAX, 0);
    gemm_nt<<<gl, 256>>>(xdq, wo, tmp, Cdim, Cdim, Cdim, Cdim,
                         1, 0, 0, 0, 0, 0, 0, os_, nullptr, 0);

    // 7. x1 = LN1(x + attn_out)
    addln_kernel<<<Mrows, 256>>>(x, tmp, x1, l1g, l1gs, l1b, l1bs);

    // 8. fc1: qdq(x1, E4M3), GEMM + bias + exact GELU fused
    qdq_kernel<<<(Mrows * Cdim / 128) / 8, 256>>>(x1, xdq, E4MAX, 1);
    dim3 gf1(MLPD / 128, Mrows / 128, 1);
    gemm_nt<<<gf1, 256>>>(xdq, fc1w, hb, Cdim, Cdim, Cdim, MLPD,
                          1, 0, 0, 0, 0, 0, 0, fc1s, fc1b, 1);

    // 9. fc2: qdq(h, E4M3), GEMM + bias
    qdq_kernel<<<(Mrows * MLPD / 128) / 8, 256>>>(hb, hdq, E4MAX, 1);
    dim3 gf2(Cdim / 128, Mrows / 128, 1);
    gemm_nt<<<gf2, 256>>>(hdq, fc2w, ffn, MLPD, MLPD, MLPD, Cdim,
                          1, 0, 0, 0, 0, 0, 0, fc2s, fc2b, 0);

    // 10. out = LN2(x1 + ffn)
    addln_kernel<<<Mrows, 256>>>(x1, ffn, out, l2g, l2gs, l2b, l2bs);
}

// round 9
// speedup vs baseline: 1.0590x; 1.0590x over previous
#include <cuda_runtime.h>
#include <cuda_fp8.h>
#include <cuda_fp16.h>
#include <math.h>

#define Bb 2
#define Tt 1024
#define Cdim 2048
#define Hh 16
#define HDim 128
#define MLPD 8192
#define Mrows (Bb * Tt)

__device__ float g_xdq[Mrows * Cdim];
__device__ float g_hdq[Mrows * MLPD];
__device__ float g_q[Mrows * Cdim];
__device__ float g_k[Mrows * Cdim];
__device__ float g_v[Mrows * Cdim];
__device__ float g_scores[(size_t)Bb * Hh * Tt * Tt];
__device__ float g_ctx[Mrows * Cdim];
__device__ float g_tmp[Mrows * Cdim];
__device__ float g_x1[Mrows * Cdim];
__device__ float g_h[Mrows * MLPD];
__device__ float g_ffn[Mrows * Cdim];

// ---------------------------------------------------------------------------
// fp32 quantize-dequantize (bit-identical to passing R1)
// ---------------------------------------------------------------------------
__global__ void qdq_kernel(const float* __restrict__ in, float* __restrict__ out,
                           float fmax, int e4m3)
{
    int blk  = blockIdx.x * 8 + (threadIdx.x >> 5);
    int lane = threadIdx.x & 31;
    size_t base = (size_t)blk * 128 + (size_t)lane * 4;
    float4 v = *reinterpret_cast<const float4*>(in + base);
    float am = fmaxf(fmaxf(fabsf(v.x), fabsf(v.y)), fmaxf(fabsf(v.z), fabsf(v.w)));
    #pragma unroll
    for (int o = 16; o > 0; o >>= 1)
        am = fmaxf(am, __shfl_xor_sync(0xffffffffu, am, o));
    float s = fmaxf(am / fmax, 1e-12f);
    float r4[4]; float xin[4] = {v.x, v.y, v.z, v.w};
    #pragma unroll
    for (int i = 0; i < 4; i++) {
        float r = xin[i] / s;
        __nv_fp8_storage_t f8 = __nv_cvt_float_to_fp8(r, __NV_SATFINITE, e4m3 ? __NV_E4M3 : __NV_E5M2);
        __half_raw hr = __nv_cvt_fp8_to_halfraw(f8, e4m3 ? __NV_E4M3 : __NV_E5M2);
        r4[i] = __half2float(*reinterpret_cast<__half*>(&hr)) * s;
    }
    float4 o4 = {r4[0], r4[1], r4[2], r4[3]};
    *reinterpret_cast<float4*>(out + base) = o4;
}

// ---------------------------------------------------------------------------
// Double-buffered fp32 SGEMM NT. One __syncthreads per BK=8 tile, register
// prefetch. Same per-thread accumulation order as R1. causal: skip n0>m0+127.
// ---------------------------------------------------------------------------
__global__ void __launch_bounds__(256, 2)
gemm_nt(const float* __restrict__ A, const float* __restrict__ W, float* __restrict__ C,
        int K, int lda, int ldb, int ldc,
        int zdiv, long long sA1, long long sA2, long long sB1, long long sB2,
        long long sC1, long long sC2,
        const float* __restrict__ wscale, const float* __restrict__ bias,
        int act, int causal)
{
    __shared__ float As[2][8][132];
    __shared__ float Bs[2][8][132];
    int z = blockIdx.z;
    int z1 = z / zdiv, z2 = z % zdiv;
    A += z1 * sA1 + z2 * sA2;
    W += z1 * sB1 + z2 * sB2;
    C += z1 * sC1 + z2 * sC2;

    int m0 = blockIdx.y * 128, n0 = blockIdx.x * 128;
    if (causal && n0 > m0 + 127) return;

    int tid = threadIdx.x;
    int tx = tid & 15, ty = tid >> 4;
    int lrow = tid >> 1, lcol = (tid & 1) * 4;
    const float* gA = A + (size_t)(m0 + lrow) * lda + lcol;
    const float* gB = W + (size_t)(n0 + lrow) * ldb + lcol;

    float acc[8][8];
    #pragma unroll
    for (int i = 0; i < 8; i++)
        #pragma unroll
        for (int j = 0; j < 8; j++) acc[i][j] = 0.0f;

    float4 av = *reinterpret_cast<const float4*>(gA);
    float4 bv = *reinterpret_cast<const float4*>(gB);
    As[0][lcol + 0][lrow] = av.x; As[0][lcol + 1][lrow] = av.y;
    As[0][lcol + 2][lrow] = av.z; As[0][lcol + 3][lrow] = av.w;
    Bs[0][lcol + 0][lrow] = bv.x; Bs[0][lcol + 1][lrow] = bv.y;
    Bs[0][lcol + 2][lrow] = bv.z; Bs[0][lcol + 3][lrow] = bv.w;
    __syncthreads();

    int nkt = K >> 3;
    for (int kt = 0; kt < nkt; kt++) {
        int cur = kt & 1;
        bool pf = (kt + 1) < nkt;
        if (pf) {
            av = *reinterpret_cast<const float4*>(gA + (kt + 1) * 8);
            bv = *reinterpret_cast<const float4*>(gB + (kt + 1) * 8);
        }
        #pragma unroll
        for (int kk = 0; kk < 8; kk++) {
            float4 a0 = *reinterpret_cast<const float4*>(&As[cur][kk][ty * 8]);
            float4 a1 = *reinterpret_cast<const float4*>(&As[cur][kk][ty * 8 + 4]);
            float4 b0 = *reinterpret_cast<const float4*>(&Bs[cur][kk][tx * 8]);
            float4 b1 = *reinterpret_cast<const float4*>(&Bs[cur][kk][tx * 8 + 4]);
            float a[8] = {a0.x, a0.y, a0.z, a0.w, a1.x, a1.y, a1.z, a1.w};
            float b[8] = {b0.x, b0.y, b0.z, b0.w, b1.x, b1.y, b1.z, b1.w};
            #pragma unroll
            for (int i = 0; i < 8; i++)
                #pragma unroll
                for (int j = 0; j < 8; j++) acc[i][j] = fmaf(a[i], b[j], acc[i][j]);
        }
        if (pf) {
            int nb = cur ^ 1;
            As[nb][lcol + 0][lrow] = av.x; As[nb][lcol + 1][lrow] = av.y;
            As[nb][lcol + 2][lrow] = av.z; As[nb][lcol + 3][lrow] = av.w;
            Bs[nb][lcol + 0][lrow] = bv.x; Bs[nb][lcol + 1][lrow] = bv.y;
            Bs[nb][lcol + 2][lrow] = bv.z; Bs[nb][lcol + 3][lrow] = bv.w;
        }
        __syncthreads();
    }

    #pragma unroll
    for (int i = 0; i < 8; i++) {
        int m = m0 + ty * 8 + i;
        #pragma unroll
        for (int j = 0; j < 8; j++) {
            int n = n0 + tx * 8 + j;
            float vv = acc[i][j];
            if (wscale) vv *= wscale[n >> 7];
            if (bias)   vv += bias[n];
            if (act)    vv = 0.5f * vv * (1.0f + erff(vv * 0.7071067811865476f));
            C[(size_t)m * ldc + n] = vv;
        }
    }
}

// ---------------------------------------------------------------------------
// Double-buffered fp32 SGEMM NN (attn @ V). Exact causal K cap at m0+128
// (attn[m,k]=0 for k>m; skipped terms are exact zeros).
// ---------------------------------------------------------------------------
__global__ void __launch_bounds__(256, 2)
gemm_nn(const float* __restrict__ A, const float* __restrict__ Bm, float* __restrict__ C,
        int K, int lda, int ldb, int ldc,
        int zdiv, long long sA1, long long sA2, long long sB1, long long sB2,
        long long sC1, long long sC2, int causal)
{
    __shared__ float As[2][8][132];
    __shared__ float Bs[2][8][132];
    int z = blockIdx.z;
    int z1 = z / zdiv, z2 = z % zdiv;
    A  += z1 * sA1 + z2 * sA2;
    Bm += z1 * sB1 + z2 * sB2;
    C  += z1 * sC1 + z2 * sC2;
    int tid = threadIdx.x;
    int tx = tid & 15, ty = tid >> 4;
    int m0 = blockIdx.y * 128, n0 = blockIdx.x * 128;
    int arow = tid >> 1, acol = (tid & 1) * 4;
    int brow = tid >> 5, bcol = (tid & 31) * 4;
    const float* gA = A + (size_t)(m0 + arow) * lda + acol;
    const float* gB = Bm + (size_t)brow * ldb + n0 + bcol;

    int Keff = causal ? (m0 + 128 < K ? m0 + 128 : K) : K;

    float acc[8][8];
    #pragma unroll
    for (int i = 0; i < 8; i++)
        #pragma unroll
        for (int j = 0; j < 8; j++) acc[i][j] = 0.0f;

    float4 av = *reinterpret_cast<const float4*>(gA);
    float4 bv = *reinterpret_cast<const float4*>(gB);
    As[0][acol + 0][arow] = av.x; As[0][acol + 1][arow] = av.y;
    As[0][acol + 2][arow] = av.z; As[0][acol + 3][arow] = av.w;
    *reinterpret_cast<float4*>(&Bs[0][brow][bcol]) = bv;
    __syncthreads();

    int nkt = Keff >> 3;
    for (int kt = 0; kt < nkt; kt++) {
        int cur = kt & 1;
        bool pf = (kt + 1) < nkt;
        if (pf) {
            av = *reinterpret_cast<const float4*>(gA + (kt + 1) * 8);
            bv = *reinterpret_cast<const float4*>(gB + (size_t)(kt + 1) * 8 * ldb);
        }
        #pragma unroll
        for (int kk = 0; kk < 8; kk++) {
            float4 a0 = *reinterpret_cast<const float4*>(&As[cur][kk][ty * 8]);
            float4 a1 = *reinterpret_cast<const float4*>(&As[cur][kk][ty * 8 + 4]);
            float4 b0 = *reinterpret_cast<const float4*>(&Bs[cur][kk][tx * 8]);
            float4 b1 = *reinterpret_cast<const float4*>(&Bs[cur][kk][tx * 8 + 4]);
            float a[8] = {a0.x, a0.y, a0.z, a0.w, a1.x, a1.y, a1.z, a1.w};
            float b[8] = {b0.x, b0.y, b0.z, b0.w, b1.x, b1.y, b1.z, b1.w};
            #pragma unroll
            for (int i = 0; i < 8; i++)
                #pragma unroll
                for (int j = 0; j < 8; j++) acc[i][j] = fmaf(a[i], b[j], acc[i][j]);
        }
        if (pf) {
            int nb = cur ^ 1;
            As[nb][acol + 0][arow] = av.x; As[nb][acol + 1][arow] = av.y;
            As[nb][acol + 2][arow] = av.z; As[nb][acol + 3][arow] = av.w;
            *reinterpret_cast<float4*>(&Bs[nb][brow][bcol]) = bv;
        }
        __syncthreads();
    }

    #pragma unroll
    for (int i = 0; i < 8; i++) {
        int m = m0 + ty * 8 + i;
        #pragma unroll
        for (int j = 0; j < 8; j++) {
            int n = n0 + tx * 8 + j;
            C[(size_t)m * ldc + n] = acc[i][j];
        }
    }
}

// ---------------------------------------------------------------------------
// Causal-masked softmax (scale folded) — verbatim R1. Masked entries
// (including never-computed score tiles) are discarded and written as 0.
// ---------------------------------------------------------------------------
__global__ void softmax_kernel(float* __restrict__ S, const int* __restrict__ mask, float scale)
{
    int row = blockIdx.x;
    int q = row % Tt;
    int b = row / (Hh * Tt);
    float* sr = S + (size_t)row * Tt;
    const int* mr = mask + ((size_t)b * Tt + q) * Tt;
    int tid = threadIdx.x;
    __shared__ float red[256];
    float vals[4];
    float lmax = -INFINITY;
    #pragma unroll
    for (int it = 0; it < 4; it++) {
        int i = tid + it * 256;
        float v = mr[i] ? sr[i] * scale : -INFINITY;
        vals[it] = v;
        lmax = fmaxf(lmax, v);
    }
    red[tid] = lmax; __syncthreads();
    for (int o = 128; o > 0; o >>= 1) {
        if (tid < o) red[tid] = fmaxf(red[tid], red[tid + o]);
        __syncthreads();
    }
    float mx = red[0];
    __syncthreads();
    float lsum = 0.0f;
    #pragma unroll
    for (int it = 0; it < 4; it++) {
        float e = expf(vals[it] - mx);
        vals[it] = e;
        lsum += e;
    }
    red[tid] = lsum; __syncthreads();
    for (int o = 128; o > 0; o >>= 1) {
        if (tid < o) red[tid] += red[tid + o];
        __syncthreads();
    }
    float inv = 1.0f / red[0];
    #pragma unroll
    for (int it = 0; it < 4; it++) {
        int i = tid + it * 256;
        sr[i] = vals[it] * inv;
    }
}

// ---------------------------------------------------------------------------
// LayerNorm(x + y) — verbatim R1
// ---------------------------------------------------------------------------
__global__ void addln_kernel(const float* __restrict__ x, const float* __restrict__ y,
                             float* __restrict__ out,
                             const float* __restrict__ g, const float* __restrict__ gs,
                             const float* __restrict__ b, const float* __restrict__ bs)
{
    int row = blockIdx.x;
    const float* xr = x + (size_t)row * Cdim;
    const float* yr = y + (size_t)row * Cdim;
    float* outr = out + (size_t)row * Cdim;
    __shared__ float buf[Cdim];
    __shared__ float red[256];
    int tid = threadIdx.x;
    float lsum = 0.0f;
    #pragma unroll
    for (int it = 0; it < Cdim / 256; it++) {
        int i = tid + it * 256;
        float v = xr[i] + yr[i];
        buf[i] = v;
        lsum += v;
    }
    red[tid] = lsum; __syncthreads();
    for (int o = 128; o > 0; o >>= 1) {
        if (tid < o) red[tid] += red[tid + o];
        __syncthreads();
    }
    float mean = red[0] * (1.0f / Cdim);
    __syncthreads();
    float lvar = 0.0f;
    #pragma unroll
    for (int it = 0; it < Cdim / 256; it++) {
        int i = tid + it * 256;
        float d = buf[i] - mean;
        lvar += d * d;
    }
    red[tid] = lvar; __syncthreads();
    for (int o = 128; o > 0; o >>= 1) {
        if (tid < o) red[tid] += red[tid + o];
        __syncthreads();
    }
    float rstd = rsqrtf(red[0] * (1.0f / Cdim) + 1e-5f);
    #pragma unroll
    for (int it = 0; it < Cdim / 256; it++) {
        int i = tid + it * 256;
        float d = (buf[i] - mean) * rstd;
        outr[i] = d * (g[i] * gs[i >> 7]) + b[i] * bs[i >> 7];
    }
}

// ---------------------------------------------------------------------------
// Launch pipeline
// ---------------------------------------------------------------------------
extern "C" void kernel_launch(void* const* d_in, const int* in_sizes, int n_in,
                              void* d_out, int out_size)
{
    const float* x     = (const float*)d_in[0];
    const int*   mask  = (const int*)  d_in[1];
    const float* wq    = (const float*)d_in[2];
    const float* qs    = (const float*)d_in[3];
    const float* wk    = (const float*)d_in[4];
    const float* ks    = (const float*)d_in[5];
    const float* wv    = (const float*)d_in[6];
    const float* vs    = (const float*)d_in[7];
    const float* wo    = (const float*)d_in[8];
    const float* os_   = (const float*)d_in[9];
    const float* fc1w  = (const float*)d_in[10];
    const float* fc1s  = (const float*)d_in[11];
    const float* fc1b  = (const float*)d_in[12];
    const float* fc2w  = (const float*)d_in[13];
    const float* fc2s  = (const float*)d_in[14];
    const float* fc2b  = (const float*)d_in[15];
    const float* l1g   = (const float*)d_in[16];
    const float* l1gs  = (const float*)d_in[17];
    const float* l1b   = (const float*)d_in[18];
    const float* l1bs  = (const float*)d_in[19];
    const float* l2g   = (const float*)d_in[20];
    const float* l2gs  = (const float*)d_in[21];
    const float* l2b   = (const float*)d_in[22];
    const float* l2bs  = (const float*)d_in[23];
    float* out = (float*)d_out;

    void* p;
    cudaGetSymbolAddress(&p, g_xdq);    float* xdq = (float*)p;
    cudaGetSymbolAddress(&p, g_hdq);    float* hdq = (float*)p;
    cudaGetSymbolAddress(&p, g_q);      float* qb  = (float*)p;
    cudaGetSymbolAddress(&p, g_k);      float* kb  = (float*)p;
    cudaGetSymbolAddress(&p, g_v);      float* vb  = (float*)p;
    cudaGetSymbolAddress(&p, g_scores); float* sc  = (float*)p;
    cudaGetSymbolAddress(&p, g_ctx);    float* ctx = (float*)p;
    cudaGetSymbolAddress(&p, g_tmp);    float* tmp = (float*)p;
    cudaGetSymbolAddress(&p, g_x1);     float* x1  = (float*)p;
    cudaGetSymbolAddress(&p, g_h);      float* hb  = (float*)p;
    cudaGetSymbolAddress(&p, g_ffn);    float* ffn = (float*)p;

    const float E5MAX = 57344.0f, E4MAX = 448.0f;
    const float INV_SQRT_HD = 0.08838834764831845f;

    // 1. qdq x (E5M2)
    qdq_kernel<<<(Mrows * Cdim / 128) / 8, 256>>>(x, xdq, E5MAX, 0);

    // 2. QKV projections
    dim3 gl(Cdim / 128, Mrows / 128, 1);
    gemm_nt<<<gl, 256>>>(xdq, wq, qb, Cdim, Cdim, Cdim, Cdim,
                         1, 0, 0, 0, 0, 0, 0, qs, nullptr, 0, 0);
    gemm_nt<<<gl, 256>>>(xdq, wk, kb, Cdim, Cdim, Cdim, Cdim,
                         1, 0, 0, 0, 0, 0, 0, ks, nullptr, 0, 0);
    gemm_nt<<<gl, 256>>>(xdq, wv, vb, Cdim, Cdim, Cdim, Cdim,
                         1, 0, 0, 0, 0, 0, 0, vs, nullptr, 0, 0);

    // 3. scores = Q @ K^T (causal tiles only)
    dim3 gsc(Tt / 128, Tt / 128, Bb * Hh);
    gemm_nt<<<gsc, 256>>>(qb, kb, sc, HDim, Cdim, Cdim, Tt,
                          Hh, (long long)Tt * Cdim, 128, (long long)Tt * Cdim, 128,
                          (long long)Hh * Tt * Tt, (long long)Tt * Tt,
                          nullptr, nullptr, 0, 1);

    // 4. masked softmax
    softmax_kernel<<<Bb * Hh * Tt, 256>>>(sc, mask, INV_SQRT_HD);

    // 5. ctx = attn @ V (K capped causally)
    dim3 gcx(1, Tt / 128, Bb * Hh);
    gemm_nn<<<gcx, 256>>>(sc, vb, ctx, Tt, Tt, Cdim, Cdim,
                          Hh, (long long)Hh * Tt * Tt, (long long)Tt * Tt,
                          (long long)Tt * Cdim, 128, (long long)Tt * Cdim, 128, 1);

    // 6. out projection
    qdq_kernel<<<(Mrows * Cdim / 128) / 8, 256>>>(ctx, xdq, E5MAX, 0);
    gemm_nt<<<gl, 256>>>(xdq, wo, tmp, Cdim, Cdim, Cdim, Cdim,
                         1, 0, 0, 0, 0, 0, 0, os_, nullptr, 0, 0);

    // 7. x1 = LN1(x + attn_out)
    addln_kernel<<<Mrows, 256>>>(x, tmp, x1, l1g, l1gs, l1b, l1bs);

    // 8. fc1 + bias + exact GELU
    qdq_kernel<<<(Mrows * Cdim / 128) / 8, 256>>>(x1, xdq, E4MAX, 1);
    dim3 gf1(MLPD / 128, Mrows / 128, 1);
    gemm_nt<<<gf1, 256>>>(xdq, fc1w, hb, Cdim, Cdim, Cdim, MLPD,
                          1, 0, 0, 0, 0, 0, 0, fc1s, fc1b, 1, 0);

    // 9. fc2 + bias
    qdq_kernel<<<(Mrows * MLPD / 128) / 8, 256>>>(hb, hdq, E4MAX, 1);
    dim3 gf2(Cdim / 128, Mrows / 128, 1);
    gemm_nt<<<gf2, 256>>>(hdq, fc2w, ffn, MLPD, MLPD, MLPD, Cdim,
                          1, 0, 0, 0, 0, 0, 0, fc2s, fc2b, 0, 0);

    // 10. out = LN2(x1 + ffn)
    addln_kernel<<<Mrows, 256>>>(x1, ffn, out, l2g, l2gs, l2b, l2bs);
}